// round 16
// baseline (speedup 1.0000x reference)
#include <cuda_runtime.h>
#include <cuda_fp16.h>

// Problem constants
#define NN 50000
#define DD 256
#define HH 4
#define CC 16
#define HC 64          // H*C
#define EE 1600000
#define NEG 0.2f

#define SCAN_B 196     // ceil(NN/256)

// ---------------- mma helper ----------------
__device__ __forceinline__ void mma16816(float* c,
                                         unsigned a0, unsigned a1,
                                         unsigned a2, unsigned a3,
                                         unsigned b0, unsigned b1) {
    asm volatile("mma.sync.aligned.m16n8k16.row.col.f32.f16.f16.f32 "
                 "{%0,%1,%2,%3}, {%4,%5,%6,%7}, {%8,%9}, {%0,%1,%2,%3};"
                 : "+f"(c[0]), "+f"(c[1]), "+f"(c[2]), "+f"(c[3])
                 : "r"(a0), "r"(a1), "r"(a2), "r"(a3), "r"(b0), "r"(b1));
}

// ---------------- device scratch ----------------
__device__ uint4    g_xh [NN * 32];        // x fp16: 256 halves/row
__device__ uint4    g_xlh[NN * 8];         // xl fp16: 64 halves/row
__device__ uint4    g_xrh[NN * 8];         // xr fp16
__device__ uint4    g_hh [NN * 8];         // h fp16 (layer-2 + output GEMM input)
__device__ uint4    g_woh[2048];           // Wo fp16: 64x256
__device__ int      g_is64;
__device__ int      g_cnt[NN];
__device__ int      g_off[NN + 1];
__device__ int      g_cur[NN];
__device__ int      g_csrc[EE];
__device__ int      g_bsum[SCAN_B];
__device__ int      g_boff[SCAN_B];

// ---------------- prep: zero cnt + cvt Wo + dtype probe (one launch) -------
__global__ void k_prep(const unsigned* __restrict__ raw,
                       const float* __restrict__ Wo) {
    int t = blockIdx.x * blockDim.x + threadIdx.x;
    if (t < NN) g_cnt[t] = 0;
    if (t < 2048) {
        const float4* p = (const float4*)Wo + t * 2;
        float4 a = p[0], b = p[1];
        __half2 h0 = __floats2half2_rn(a.x, a.y), h1 = __floats2half2_rn(a.z, a.w);
        __half2 h2 = __floats2half2_rn(b.x, b.y), h3 = __floats2half2_rn(b.z, b.w);
        uint4 u;
        u.x = *(unsigned*)&h0; u.y = *(unsigned*)&h1;
        u.z = *(unsigned*)&h2; u.w = *(unsigned*)&h3;
        g_woh[t] = u;
    }
    if (blockIdx.x == gridDim.x - 1 && threadIdx.x < 32) {
        unsigned any = 0;
        for (int i = threadIdx.x; i < 256; i += 32) any |= raw[2 * i + 1];
#pragma unroll
        for (int o = 16; o; o >>= 1) any |= __shfl_xor_sync(0xffffffffu, any, o);
        if (threadIdx.x == 0) g_is64 = (any == 0) ? 1 : 0;
    }
}

// ---------------- X fp32 -> fp16 ----------------
__global__ void k_cvt_x(const float* __restrict__ x) {
    int t = blockIdx.x * blockDim.x + threadIdx.x;
    if (t >= NN * 32) return;
    const float4* p = (const float4*)x + t * 2;
    float4 a = p[0], b = p[1];
    __half2 h0 = __floats2half2_rn(a.x, a.y), h1 = __floats2half2_rn(a.z, a.w);
    __half2 h2 = __floats2half2_rn(b.x, b.y), h3 = __floats2half2_rn(b.z, b.w);
    uint4 u;
    u.x = *(unsigned*)&h0; u.y = *(unsigned*)&h1;
    u.z = *(unsigned*)&h2; u.w = *(unsigned*)&h3;
    g_xh[t] = u;
}

__global__ void k_hist(const void* __restrict__ eiv) {
    int e = blockIdx.x * blockDim.x + threadIdx.x;
    if (e >= EE) return;
    int d;
    if (g_is64) d = (int)((const long long*)eiv)[EE + e];
    else        d = ((const int*)eiv)[EE + e];
    d = min(max(d, 0), NN - 1);
    atomicAdd(&g_cnt[d], 1);
}

// ---------------- multi-block exclusive scan ----------------
__global__ void k_scan_a() {
    int i = blockIdx.x * 256 + threadIdx.x;
    int c = (i < NN) ? g_cnt[i] : 0;
    int lane = threadIdx.x & 31, w = threadIdx.x >> 5;
#pragma unroll
    for (int o = 16; o; o >>= 1) c += __shfl_xor_sync(0xffffffffu, c, o);
    __shared__ int ws[8];
    if (lane == 0) ws[w] = c;
    __syncthreads();
    if (threadIdx.x == 0) {
        int s = 0;
#pragma unroll
        for (int k = 0; k < 8; k++) s += ws[k];
        g_bsum[blockIdx.x] = s;
    }
}

__global__ void k_scan_b() {
    int t = threadIdx.x;
    int v = (t < SCAN_B) ? g_bsum[t] : 0;
    int c = v;
    int lane = t & 31, w = t >> 5;
#pragma unroll
    for (int o = 1; o < 32; o <<= 1) {
        int u = __shfl_up_sync(0xffffffffu, v, o);
        if (lane >= o) v += u;
    }
    __shared__ int ws[8];
    if (lane == 31) ws[w] = v;
    __syncthreads();
    if (w == 0) {
        int s = (lane < 8) ? ws[lane] : 0;
#pragma unroll
        for (int o = 1; o < 8; o <<= 1) {
            int u = __shfl_up_sync(0xffffffffu, s, o);
            if (lane >= o) s += u;
        }
        if (lane < 8) ws[lane] = s;
    }
    __syncthreads();
    int incl = v + (w > 0 ? ws[w - 1] : 0);
    if (t < SCAN_B) g_boff[t] = incl - c;
}

__global__ void k_scan_c() {
    int i = blockIdx.x * 256 + threadIdx.x;
    int c = (i < NN) ? g_cnt[i] : 0;
    int v = c;
    int lane = threadIdx.x & 31, w = threadIdx.x >> 5;
#pragma unroll
    for (int o = 1; o < 32; o <<= 1) {
        int u = __shfl_up_sync(0xffffffffu, v, o);
        if (lane >= o) v += u;
    }
    __shared__ int ws[8];
    if (lane == 31) ws[w] = v;
    __syncthreads();
    if (w == 0) {
        int s = (lane < 8) ? ws[lane] : 0;
#pragma unroll
        for (int o = 1; o < 8; o <<= 1) {
            int u = __shfl_up_sync(0xffffffffu, s, o);
            if (lane >= o) s += u;
        }
        if (lane < 8) ws[lane] = s;
    }
    __syncthreads();
    int excl = v - c + (w > 0 ? ws[w - 1] : 0) + g_boff[blockIdx.x];
    if (i < NN) { g_off[i] = excl; g_cur[i] = excl; }
    if (i == 0) g_off[NN] = EE;
}

__global__ void k_scatter(const void* __restrict__ eiv) {
    int e = blockIdx.x * blockDim.x + threadIdx.x;
    if (e >= EE) return;
    int s, d;
    if (g_is64) {
        const long long* p = (const long long*)eiv;
        s = (int)p[e]; d = (int)p[EE + e];
    } else {
        const int* p = (const int*)eiv;
        s = p[e]; d = p[EE + e];
    }
    s = min(max(s, 0), NN - 1);
    d = min(max(d, 0), NN - 1);
    int pos = atomicAdd(&g_cur[d], 1);
    g_csrc[pos] = s;
}

// ---------------- tensor-core dual GEMM, K-stage = 64, fp16 inputs ---------
__global__ void __launch_bounds__(256, 2)
k_gemm2t(int layer,
         const float* __restrict__ Wl, const float* __restrict__ bl,
         const float* __restrict__ Wr, const float* __restrict__ br,
         int Fin) {
    __shared__ __align__(16) __half sX [128 * 72];   // 18 KB
    __shared__ __align__(16) __half sWl[64 * 64];    // 8 KB (swizzled rows)
    __shared__ __align__(16) __half sWr[64 * 64];    // 8 KB

    const uint4* Xh = layer ? g_hh : g_xh;
    int xstr = layer ? 8 : 32;

    int tid = threadIdx.x;
    int warp = tid >> 5, lane = tid & 31;
    int r0 = blockIdx.x * 128;

    float acc[16][4];
#pragma unroll
    for (int i = 0; i < 16; i++)
#pragma unroll
        for (int j = 0; j < 4; j++) acc[i][j] = 0.f;

    unsigned bsX  = (unsigned)__cvta_generic_to_shared(sX);
    unsigned bsWl = (unsigned)__cvta_generic_to_shared(sWl);
    unsigned bsWr = (unsigned)__cvta_generic_to_shared(sWr);

    int brr = lane & 15;
    int bcc = (lane >> 4) * 8;

    int srow = tid >> 1, shf = tid & 1;
    int wrow = tid >> 2, wqg = tid & 3;

    for (int k0 = 0; k0 < Fin; k0 += 64) {
        {
            int gr = r0 + srow;
            int base = gr * xstr + (k0 >> 3) + shf * 4;
#pragma unroll
            for (int i = 0; i < 4; i++) {
                uint4 st = make_uint4(0u, 0u, 0u, 0u);
                if (gr < NN) st = Xh[base + i];
                *(uint4*)&sX[srow * 72 + (shf * 4 + i) * 8] = st;
            }
        }
#pragma unroll
        for (int mat = 0; mat < 2; mat++) {
            const float* W = mat ? Wr : Wl;
            __half* sW = mat ? sWr : sWl;
#pragma unroll
            for (int i = 0; i < 4; i++) {
                int quad = wqg * 4 + i;
                float4 v = *(const float4*)(W + (k0 + wrow) * HC + quad * 4);
                __half2 h01 = __floats2half2_rn(v.x, v.y);
                __half2 h23 = __floats2half2_rn(v.z, v.w);
                int off = wrow * 128 + quad * 8;
                off ^= ((off >> 7) & 7) << 4;
                uint2 st; st.x = *(unsigned*)&h01; st.y = *(unsigned*)&h23;
                *(uint2*)((char*)sW + off) = st;
            }
        }
        __syncthreads();

#pragma unroll
        for (int ks = 0; ks < 4; ks++) {
            unsigned aAddr = bsX +
                ((warp * 16 + (lane & 15)) * 72 + ks * 16 + (lane >> 4) * 8) * 2;
            unsigned a0, a1, a2, a3;
            asm volatile("ldmatrix.sync.aligned.m8n8.x4.shared.b16 {%0,%1,%2,%3}, [%4];"
                         : "=r"(a0), "=r"(a1), "=r"(a2), "=r"(a3) : "r"(aAddr));
#pragma unroll
            for (int mat = 0; mat < 2; mat++) {
                unsigned base = mat ? bsWr : bsWl;
#pragma unroll
                for (int gp = 0; gp < 4; gp++) {
                    int off = (ks * 16 + brr) * 128 + (gp * 16 + bcc) * 2;
                    off ^= ((off >> 7) & 7) << 4;
                    unsigned b0, b1, b2, b3;
                    asm volatile("ldmatrix.sync.aligned.m8n8.x4.trans.shared.b16 {%0,%1,%2,%3}, [%4];"
                                 : "=r"(b0), "=r"(b1), "=r"(b2), "=r"(b3)
                                 : "r"(base + (unsigned)off));
                    mma16816(acc[mat * 8 + gp * 2],     a0, a1, a2, a3, b0, b1);
                    mma16816(acc[mat * 8 + gp * 2 + 1], a0, a1, a2, a3, b2, b3);
                }
            }
        }
        __syncthreads();
    }

    int gid = lane >> 2, t4 = lane & 3;
    int row0 = r0 + warp * 16 + gid;
    int row1 = row0 + 8;
#pragma unroll
    for (int mat = 0; mat < 2; mat++) {
        const float* B = mat ? br : bl;
        unsigned* T = (unsigned*)(mat ? g_xrh : g_xlh);
#pragma unroll
        for (int g = 0; g < 8; g++) {
            int col = g * 8 + t4 * 2;
            float b0v = __ldg(B + col), b1v = __ldg(B + col + 1);
            float* c = acc[mat * 8 + g];
            __half2 h0 = __floats2half2_rn(c[0] + b0v, c[1] + b1v);
            __half2 h1 = __floats2half2_rn(c[2] + b0v, c[3] + b1v);
            if (row0 < NN) T[row0 * 32 + (col >> 1)] = *(unsigned*)&h0;
            if (row1 < NN) T[row1 * 32 + (col >> 1)] = *(unsigned*)&h1;
        }
    }
}

// ---------------- CSR gather-agg: warp/node, 8 slots x 4 lanes --------------
// Lane j = lane&3 owns head j (16 channels) -> the logit is a LOCAL dot
// product, no shuffles in the loop body. slot = lane>>2 (8 edges in flight).
// 1-deep prefetch of src index + xl payload (2 x uint4 per lane).
__global__ void k_edge_csr(const float* __restrict__ att,
                           const float* __restrict__ bias) {
    int warp = (blockIdx.x * blockDim.x + threadIdx.x) >> 5;
    if (warp >= NN) return;
    int lane = threadIdx.x & 31;
    int j = lane & 3;          // head
    int slot = lane >> 2;      // edge slot 0..7

    // xr: 16 channels of head j
    uint4 ur0 = g_xrh[warp * 8 + 2 * j];
    uint4 ur1 = g_xrh[warp * 8 + 2 * j + 1];
    float r[16];
    {
        float2 t;
        t = __half22float2(*(__half2*)&ur0.x); r[0] = t.x; r[1] = t.y;
        t = __half22float2(*(__half2*)&ur0.y); r[2] = t.x; r[3] = t.y;
        t = __half22float2(*(__half2*)&ur0.z); r[4] = t.x; r[5] = t.y;
        t = __half22float2(*(__half2*)&ur0.w); r[6] = t.x; r[7] = t.y;
        t = __half22float2(*(__half2*)&ur1.x); r[8] = t.x; r[9] = t.y;
        t = __half22float2(*(__half2*)&ur1.y); r[10] = t.x; r[11] = t.y;
        t = __half22float2(*(__half2*)&ur1.z); r[12] = t.x; r[13] = t.y;
        t = __half22float2(*(__half2*)&ur1.w); r[14] = t.x; r[15] = t.y;
    }
    float a[16];
#pragma unroll
    for (int c = 0; c < 16; c++) a[c] = __ldg(att + 16 * j + c);

    int beg = g_off[warp];
    int end = g_off[warp + 1];
    int iters = (end - beg + 7) >> 3;

    float acc[16];
#pragma unroll
    for (int c = 0; c < 16; c++) acc[c] = 0.f;
    float den = 0.f;

    int p = beg + slot;
    bool valid = p < end;
    int src = valid ? __ldg(&g_csrc[p]) : 0;
    uint4 ux0 = g_xlh[src * 8 + 2 * j];
    uint4 ux1 = g_xlh[src * 8 + 2 * j + 1];

    for (int it = 0; it < iters; it++) {
        bool v_cur = valid;
        uint4 c0 = ux0, c1 = ux1;
        p += 8;
        valid = p < end;
        src = valid ? __ldg(&g_csrc[p]) : 0;
        ux0 = g_xlh[src * 8 + 2 * j];
        ux1 = g_xlh[src * 8 + 2 * j + 1];   // prefetch next payload

        float l[16];
        {
            float2 t;
            t = __half22float2(*(__half2*)&c0.x); l[0] = t.x; l[1] = t.y;
            t = __half22float2(*(__half2*)&c0.y); l[2] = t.x; l[3] = t.y;
            t = __half22float2(*(__half2*)&c0.z); l[4] = t.x; l[5] = t.y;
            t = __half22float2(*(__half2*)&c0.w); l[6] = t.x; l[7] = t.y;
            t = __half22float2(*(__half2*)&c1.x); l[8] = t.x; l[9] = t.y;
            t = __half22float2(*(__half2*)&c1.y); l[10] = t.x; l[11] = t.y;
            t = __half22float2(*(__half2*)&c1.z); l[12] = t.x; l[13] = t.y;
            t = __half22float2(*(__half2*)&c1.w); l[14] = t.x; l[15] = t.y;
        }

        float s = 0.f;
#pragma unroll
        for (int c = 0; c < 16; c++) {
            float v = l[c] + r[c];
            v = v > 0.f ? v : NEG * v;
            s = fmaf(v, a[c], s);
        }

        float ex = v_cur ? __expf(fminf(s, 75.f)) : 0.f;
        den += ex;
#pragma unroll
        for (int c = 0; c < 16; c++) acc[c] = fmaf(ex, l[c], acc[c]);
    }

    // combine the 8 edge-slots (lane bits 2,3,4)
#pragma unroll
    for (int c = 0; c < 16; c++) {
        acc[c] += __shfl_xor_sync(0xffffffffu, acc[c], 4);
        acc[c] += __shfl_xor_sync(0xffffffffu, acc[c], 8);
        acc[c] += __shfl_xor_sync(0xffffffffu, acc[c], 16);
    }
    den += __shfl_xor_sync(0xffffffffu, den, 4);
    den += __shfl_xor_sync(0xffffffffu, den, 8);
    den += __shfl_xor_sync(0xffffffffu, den, 16);

    if (slot == 0) {
        float inv = (den > 0.f) ? (1.f / den) : 0.f;
        float o[16];
#pragma unroll
        for (int c = 0; c < 16; c++)
            o[c] = fmaxf(fmaf(acc[c], inv, __ldg(bias + 16 * j + c)), 0.f);
        __half2 q0 = __floats2half2_rn(o[0], o[1]);
        __half2 q1 = __floats2half2_rn(o[2], o[3]);
        __half2 q2 = __floats2half2_rn(o[4], o[5]);
        __half2 q3 = __floats2half2_rn(o[6], o[7]);
        __half2 q4 = __floats2half2_rn(o[8], o[9]);
        __half2 q5 = __floats2half2_rn(o[10], o[11]);
        __half2 q6 = __floats2half2_rn(o[12], o[13]);
        __half2 q7 = __floats2half2_rn(o[14], o[15]);
        uint4 u0, u1;
        u0.x = *(unsigned*)&q0; u0.y = *(unsigned*)&q1;
        u0.z = *(unsigned*)&q2; u0.w = *(unsigned*)&q3;
        u1.x = *(unsigned*)&q4; u1.y = *(unsigned*)&q5;
        u1.z = *(unsigned*)&q6; u1.w = *(unsigned*)&q7;
        g_hh[warp * 8 + 2 * j]     = u0;
        g_hh[warp * 8 + 2 * j + 1] = u1;
    }
}

// ---------------- tensor-core output head: sigmoid(h @ Wo + bo) -------------
__global__ void __launch_bounds__(256, 2)
k_outt(const float* __restrict__ bo, float* __restrict__ out) {
    __shared__ __align__(16) __half sX [128 * 72];   // 18 KB
    __shared__ __align__(16) __half sWo[64 * 128];   // 16 KB

    int tid = threadIdx.x;
    int warp = tid >> 5, lane = tid & 31;
    int r0 = blockIdx.x * 128;
    int cb = blockIdx.y * 128;

    float acc[16][4];
#pragma unroll
    for (int i = 0; i < 16; i++)
#pragma unroll
        for (int j = 0; j < 4; j++) acc[i][j] = 0.f;

    unsigned bsX = (unsigned)__cvta_generic_to_shared(sX);
    unsigned bsW = (unsigned)__cvta_generic_to_shared(sWo);

    {
        int srow = tid >> 1, shf = tid & 1;
        int gr = r0 + srow;
#pragma unroll
        for (int i = 0; i < 4; i++) {
            uint4 st = make_uint4(0u, 0u, 0u, 0u);
            if (gr < NN) st = g_hh[gr * 8 + shf * 4 + i];
            *(uint4*)&sX[srow * 72 + (shf * 4 + i) * 8] = st;
        }
    }
    {
        const __half* Wh = (const __half*)g_woh;
#pragma unroll
        for (int c = tid; c < 1024; c += 256) {
            int row = c >> 4, q = c & 15;
            uint4 v = *(const uint4*)(Wh + row * DD + cb + q * 8);
            int off = row * 256 + q * 16;
            off ^= ((off >> 8) & 7) << 4;
            *(uint4*)((char*)sWo + off) = v;
        }
    }
    __syncthreads();

    int brr = lane & 15;
    int bcc = (lane >> 4) * 8;

#pragma unroll
    for (int ks = 0; ks < 4; ks++) {
        unsigned aAddr = bsX +
            ((warp * 16 + (lane & 15)) * 72 + ks * 16 + (lane >> 4) * 8) * 2;
        unsigned a0, a1, a2, a3;
        asm volatile("ldmatrix.sync.aligned.m8n8.x4.shared.b16 {%0,%1,%2,%3}, [%4];"
                     : "=r"(a0), "=r"(a1), "=r"(a2), "=r"(a3) : "r"(aAddr));
#pragma unroll
        for (int gp = 0; gp < 8; gp++) {
            int off = (ks * 16 + brr) * 256 + (gp * 16 + bcc) * 2;
            off ^= ((off >> 8) & 7) << 4;
            unsigned b0, b1, b2, b3;
            asm volatile("ldmatrix.sync.aligned.m8n8.x4.trans.shared.b16 {%0,%1,%2,%3}, [%4];"
                         : "=r"(b0), "=r"(b1), "=r"(b2), "=r"(b3)
                         : "r"(bsW + (unsigned)off));
            mma16816(acc[gp * 2],     a0, a1, a2, a3, b0, b1);
            mma16816(acc[gp * 2 + 1], a0, a1, a2, a3, b2, b3);
        }
    }

    int gid = lane >> 2, t4 = lane & 3;
    int row0 = r0 + warp * 16 + gid;
    int row1 = row0 + 8;
#pragma unroll
    for (int g = 0; g < 16; g++) {
        int col = cb + g * 8 + t4 * 2;
        float b0v = __ldg(bo + col), b1v = __ldg(bo + col + 1);
        float* c = acc[g];
        if (row0 < NN) {
            float2 o;
            o.x = 1.f / (1.f + __expf(-(c[0] + b0v)));
            o.y = 1.f / (1.f + __expf(-(c[1] + b1v)));
            *(float2*)(out + (long)row0 * DD + col) = o;
        }
        if (row1 < NN) {
            float2 o;
            o.x = 1.f / (1.f + __expf(-(c[2] + b0v)));
            o.y = 1.f / (1.f + __expf(-(c[3] + b1v)));
            *(float2*)(out + (long)row1 * DD + col) = o;
        }
    }
}

// ---------------- launcher ----------------
extern "C" void kernel_launch(void* const* d_in, const int* in_sizes, int n_in,
                              void* d_out, int out_size) {
    const float* x    = (const float*)d_in[0];
    const void*  ei   = d_in[1];
    const float* Wl1  = (const float*)d_in[2];
    const float* bl1  = (const float*)d_in[3];
    const float* Wr1  = (const float*)d_in[4];
    const float* br1  = (const float*)d_in[5];
    const float* att1 = (const float*)d_in[6];
    const float* bias1= (const float*)d_in[7];
    const float* Wl2  = (const float*)d_in[8];
    const float* bl2  = (const float*)d_in[9];
    const float* Wr2  = (const float*)d_in[10];
    const float* br2  = (const float*)d_in[11];
    const float* att2 = (const float*)d_in[12];
    const float* bias2= (const float*)d_in[13];
    const float* Wo   = (const float*)d_in[14];
    const float* bo   = (const float*)d_in[15];
    float* out = (float*)d_out;

    const int TB = 256;
    const int gE    = (EE + TB - 1) / TB;
    const int gTile = (NN + 127) / 128;          // 391
    const int gWarp = (NN * 32 + TB - 1) / TB;

    k_prep<<<SCAN_B, TB>>>((const unsigned*)ei, Wo);
    k_cvt_x<<<(NN * 32 + TB - 1) / TB, TB>>>(x);
    k_hist<<<gE, TB>>>(ei);
    k_gemm2t<<<gTile, TB>>>(0, Wl1, bl1, Wr1, br1, DD);  // layer-1
    k_scan_a<<<SCAN_B, 256>>>();
    k_scan_b<<<1, 256>>>();
    k_scan_c<<<SCAN_B, 256>>>();
    k_scatter<<<gE, TB>>>(ei);

    // ---- layer 1 edge phase ----
    k_edge_csr<<<gWarp, TB>>>(att1, bias1);

    // ---- layer 2 ----
    k_gemm2t<<<gTile, TB>>>(1, Wl2, bl2, Wr2, br2, HC);
    k_edge_csr<<<gWarp, TB>>>(att2, bias2);

    // ---- output head ----
    k_outt<<<dim3(gTile, 2), TB>>>(bo, out);
}